// round 6
// baseline (speedup 1.0000x reference)
#include <cuda_runtime.h>
#include <cstdint>

// VoltageNet: B=512 batches, T=8192 timesteps. One CTA/batch, 512 thr, 16 steps/thr.
// R5: 2 CTAs/SM (regs<=64 via smem staging of per-step state), sigmoid via tanh.approx.

#define TT 8192
#define NT 512
#define LL 16
#define FULL 0xFFFFFFFFu
// dynamic smem: float2 sAB[TT] (64KB) + float sV[TT + TT/16] (34.8KB)
#define SMEM_BYTES ((2 * TT + TT + TT / 16) * 4)

__device__ __forceinline__ float tanh_fast(float x) {
    float y; asm("tanh.approx.f32 %0, %1;" : "=f"(y) : "f"(x)); return y;
}
// sigmoid(z) = 0.5 * (1 + tanh(z/2))  — one MUFU op
__device__ __forceinline__ float sigmoid_f(float z) {
    return fmaf(tanh_fast(0.5f * z), 0.5f, 0.5f);
}
__device__ __forceinline__ float softplus_f(float x) {
    return fmaxf(x, 0.0f) + __logf(1.0f + __expf(-fabsf(x)));
}

__global__ __launch_bounds__(NT, 2)
void voltage_kernel(const float* __restrict__ X, const float* __restrict__ SC,
                    const float* __restrict__ W1g, const float* __restrict__ b1g,
                    const float* __restrict__ W2g, const float* __restrict__ b2g,
                    float* __restrict__ out)
{
    extern __shared__ float smem[];
    float2* sAB = reinterpret_cast<float2*>(smem);   // phase0: (I, ds); phase1+: (a, b)
    float*  sV  = smem + 2 * TT;                     // skewed: slot(t) = t + (t>>4)

    __shared__ float sWS[16], sWA[16], sWB[16], sTr[16];
    __shared__ float sW10[6], sC1[6], sW2[24], sB2[4];
    __shared__ float sTmean, sU10;

    const int tid  = threadIdx.x;
    const int lane = tid & 31;
    const int wid  = tid >> 5;
    const int b    = blockIdx.x;
    const int base = tid * LL;

    const float Q  = SC[2 * b + 0];
    const float R0 = SC[2 * b + 1];

    // stage MLP constants (cols 0,1,5,6 of W2)
    if (tid < 6) sW10[tid] = W1g[tid];
    if (tid >= 32 && tid < 56) {
        int i = (tid - 32) >> 2, c = (tid - 32) & 3;
        const int col[4] = {0, 1, 5, 6};
        sW2[tid - 32] = W2g[i * 7 + col[c]];
    }
    if (tid >= 64 && tid < 68) {
        const int col[4] = {0, 1, 5, 6};
        sB2[tid - 64] = b2g[col[tid - 64]];
    }

    // ---------- phase 0: load 16 steps in two 6xfloat4 chunks, stage (I, ds) ----------
    const float invC = 1.0f / 36000.0f;  // 1/(2*3600*QN)
    float tsum = 0.0f, dsum = 0.0f;
    float pt = 0.0f, pI = 0.0f;
    {
        const float4* px = reinterpret_cast<const float4*>(X + ((size_t)b * TT + base) * 3);
#pragma unroll
        for (int c = 0; c < 2; c++) {
            float4 v[6];
#pragma unroll
            for (int i = 0; i < 6; i++) v[i] = px[c * 6 + i];
            const float* f = reinterpret_cast<const float*>(v);
#pragma unroll
            for (int j = 0; j < 8; j++) {
                int s = c * 8 + j;
                float t = f[3 * j], I = f[3 * j + 1], Te = f[3 * j + 2];
                tsum += Te;
                if (s > 0) {
                    float d = (I + pI) * (t - pt) * invC;
                    dsum += d;
                    sAB[base + s - 1] = make_float2(pI, d);
                }
                pt = t; pI = I;
            }
        }
    }
    float t16 = pt, I16 = pI;   // clamp at end -> ds=0, a=1, b=0
    if (tid < NT - 1) {
        float2 e = *reinterpret_cast<const float2*>(X + ((size_t)b * TT + base + LL) * 3);
        t16 = e.x; I16 = e.y;
    }
    {
        float d = (I16 + pI) * (t16 - pt) * invC;
        dsum += d;
        sAB[base + LL - 1] = make_float2(pI, d);
    }

    // ---------- block scan of dsum, reduce tsum ----------
    float v = dsum;
#pragma unroll
    for (int o = 1; o < 32; o <<= 1) {
        float n = __shfl_up_sync(FULL, v, o);
        if (lane >= o) v += n;
    }
    float excl = __shfl_up_sync(FULL, v, 1);
    if (lane == 0) excl = 0.0f;
#pragma unroll
    for (int o = 16; o > 0; o >>= 1) tsum += __shfl_down_sync(FULL, tsum, o);
    if (lane == 31) sWS[wid] = v;
    if (lane == 0)  sTr[wid] = tsum;
    __syncthreads();

    if (tid < 32) {
        float w = (lane < 16) ? sWS[lane] : 0.0f;
#pragma unroll
        for (int o = 1; o < 16; o <<= 1) {
            float n = __shfl_up_sync(FULL, w, o);
            if (lane >= o) w += n;
        }
        float e = __shfl_up_sync(FULL, w, 1);
        if (lane == 0) e = 0.0f;
        if (lane < 16) sWS[lane] = e;
        float ts = (lane < 16) ? sTr[lane] : 0.0f;
#pragma unroll
        for (int o = 16; o > 0; o >>= 1) ts += __shfl_down_sync(FULL, ts, o);
        if (lane == 0) sTmean = ts * (1.0f / TT);
    }
    __syncthreads();
    if (tid < 6)
        sC1[tid] = fmaf(R0, W1g[6 + tid], fmaf(sTmean, W1g[12 + tid], b1g[tid]));
    __syncthreads();

    // U1(0): theta2 (OCV_U) at soc0  (before slot 0 gets overwritten)
    if (tid == 0) {
        float soc0 = Q * 0.2f;
        float p2 = b2g[2];
#pragma unroll
        for (int j = 0; j < 6; j++) {
            float h = softplus_f(fmaf(soc0, sW10[j], sC1[j]));
            p2 = fmaf(h, W2g[j * 7 + 2], p2);
        }
        float th2 = fmaf(0.75f, sigmoid_f(0.01f * p2), 0.05f);
        sU10 = -th2 - sAB[0].x * R0;
    }

    // ---------- phase 1: MLP + OCV per step; write (a,b); compose (A,B) ----------
    float soc = fmaf(Q, 0.2f, sWS[wid] + excl);
    float A = 1.0f, Bc = 0.0f;
    float2 cur = sAB[base];
#pragma unroll
    for (int k = 0; k < LL; k++) {
        float2 nxt = (k < LL - 1) ? sAB[base + k + 1] : make_float2(I16, 0.0f);
        float Ik = cur.x, dsk = cur.y;

        float p0 = sB2[0], p1 = sB2[1], p5 = sB2[2], p6 = sB2[3];
#pragma unroll
        for (int j = 0; j < 6; j++) {
            float h = softplus_f(fmaf(soc, sW10[j], sC1[j]));
            p0 = fmaf(h, sW2[j * 4 + 0], p0);
            p1 = fmaf(h, sW2[j * 4 + 1], p1);
            p5 = fmaf(h, sW2[j * 4 + 2], p5);
            p6 = fmaf(h, sW2[j * 4 + 3], p6);
        }
        float R1 = 0.04f * sigmoid_f(0.01f * p0);
        float C  = 1e-6f * sigmoid_f(0.01f * p1);
        float ox = fmaf(0.79764f, sigmoid_f(0.01f * p5), 0.04236f);
        float oy = fmaf(0.82504f, sigmoid_f(0.01f * p6), 0.023f);

        float up = 4.4167f + oy * (-1.6518f + oy * (1.6225f + oy * (-2.0843f + oy * (3.5146f + oy * (-2.2166f)))));
        up -= 4.0f * __expf(fmaf(109.451f, oy, -100.006f));
        float un = 0.063f + 0.8f * __expf(-75.0f * (ox + 0.001f));
        un -= 0.012f  * tanh_fast(fmaf(ox, 62.5f, -7.9375f));
        un -= 0.0118f * tanh_fast(fmaf(ox, 62.5f, -9.6875f));
        un -= 0.0035f * tanh_fast(fmaf(ox, 50.0f, -11.0f));
        un -= 0.0095f * tanh_fast(fmaf(ox, 76.923076923f, -14.6153846154f));
        un -= 0.0145f * tanh_fast(fmaf(ox, 50.0f, -24.5f));
        un -= 0.08f   * tanh_fast(fmaf(ox, 18.1818181818f, -18.7272727273f));

        int t = base + k;
        sV[t + (t >> 4)] = up - un + Ik * R0;   // OCV + I*R0 folded

        float dt = nxt.x - Ik;
        float g  = dt * C;
        float a  = 1.0f - g;
        float bb = g * R1 * Ik;
        sAB[base + k] = make_float2(a, bb);
        Bc = fmaf(a, Bc, bb);
        A *= a;

        soc += dsk;
        cur = nxt;
    }

    // ---------- phase 2: block affine scan over (A,B) ----------
#pragma unroll
    for (int o = 1; o < 32; o <<= 1) {
        float Ao = __shfl_up_sync(FULL, A, o);
        float Bo = __shfl_up_sync(FULL, Bc, o);
        if (lane >= o) { Bc = fmaf(A, Bo, Bc); A = A * Ao; }
    }
    float Ax = __shfl_up_sync(FULL, A, 1);
    float Bx = __shfl_up_sync(FULL, Bc, 1);
    if (lane == 0) { Ax = 1.0f; Bx = 0.0f; }
    if (lane == 31) { sWA[wid] = A; sWB[wid] = Bc; }
    __syncthreads();
    if (tid < 32) {
        float wA = (lane < 16) ? sWA[lane] : 1.0f;
        float wB = (lane < 16) ? sWB[lane] : 0.0f;
#pragma unroll
        for (int o = 1; o < 16; o <<= 1) {
            float Ao = __shfl_up_sync(FULL, wA, o);
            float Bo = __shfl_up_sync(FULL, wB, o);
            if (lane >= o) { wB = fmaf(wA, Bo, wB); wA = wA * Ao; }
        }
        float eA = __shfl_up_sync(FULL, wA, 1);
        float eB = __shfl_up_sync(FULL, wB, 1);
        if (lane == 0) { eA = 1.0f; eB = 0.0f; }
        if (lane < 16) { sWA[lane] = eA; sWB[lane] = eB; }
    }
    __syncthreads();
    float wA = sWA[wid], wB = sWB[wid];
    float EA = Ax * wA;
    float EB = fmaf(Ax, wB, Bx);
    float U1 = fmaf(EA, sU10, EB);

    // ---------- phase 3: replay U1, finalize, coalesced store ----------
#pragma unroll
    for (int k = 0; k < LL; k++) {
        int t = base + k;
        float2 ab = sAB[base + k];
        sV[t + (t >> 4)] += U1;
        U1 = fmaf(ab.x, U1, ab.y);
    }
    __syncthreads();
    float* ob = out + (size_t)b * TT;
#pragma unroll
    for (int i = 0; i < LL; i++) {
        int idx = tid + i * NT;
        ob[idx] = sV[idx + (idx >> 4)];
    }
}

extern "C" void kernel_launch(void* const* d_in, const int* in_sizes, int n_in,
                              void* d_out, int out_size)
{
    const float* X  = (const float*)d_in[0];
    const float* SC = (const float*)d_in[1];
    const float* W1 = (const float*)d_in[2];
    const float* b1 = (const float*)d_in[3];
    const float* W2 = (const float*)d_in[4];
    const float* b2 = (const float*)d_in[5];
    int B = in_sizes[1] / 2;   // SC is (B,2)
    cudaFuncSetAttribute(voltage_kernel,
                         cudaFuncAttributeMaxDynamicSharedMemorySize, SMEM_BYTES);
    voltage_kernel<<<B, NT, SMEM_BYTES>>>(X, SC, W1, b1, W2, b2, (float*)d_out);
}